// round 16
// baseline (speedup 1.0000x reference)
#include <cuda_runtime.h>
#include <cuda_bf16.h>
#include <cstdint>
#include <math.h>

#define BATCH 4
#define NPTS  8192
#define DIM   128
#define DOUT  256
#define NH    4
#define HD    64
#define KNBR  16
#define ROWS  (BATCH*NPTS)          // 32768
#define NROWS (BATCH*NPTS*KNBR)     // 524288

// ---------------- scratch ----------------
__device__ float4 g_xyzw[ROWS];
__device__ int    g_knn[NROWS];
__device__ float  g_T[ROWS];
__device__ __nv_bfloat16 g_kA[(size_t)ROWS*32];
__device__ __nv_bfloat16 g_kB[(size_t)ROWS*32];
__device__ __nv_bfloat16 g_feat_h[ROWS*DIM];
__device__ __nv_bfloat16 g_feat_l[ROWS*DIM];
__device__ __nv_bfloat16 g_lnf_h[ROWS*DIM];
__device__ __nv_bfloat16 g_lnf_l[ROWS*DIM];
__device__ float  g_qf[(size_t)ROWS*DOUT];
__device__ __nv_bfloat16 g_kvb[(size_t)ROWS*DOUT];
__device__ float  g_vf[(size_t)ROWS*DOUT];
__device__ float  g_lnq[ROWS*DOUT];
__device__ __nv_bfloat16 g_posb[(size_t)NROWS*HD];
__device__ __nv_bfloat16 g_mid_h[ROWS*DOUT];
__device__ __nv_bfloat16 g_mid_l[ROWS*DOUT];
__device__ __nv_bfloat16 g_fc1_h[ROWS*DOUT];
__device__ __nv_bfloat16 g_fc1_l[ROWS*DOUT];
__device__ float  g_fc2[ROWS*DOUT];
__device__ __nv_bfloat16 g_wqkvT_h[768*DIM];
__device__ __nv_bfloat16 g_wqkvT_l[768*DIM];
__device__ __nv_bfloat16 g_wp2T_h[HD*HD];
__device__ __nv_bfloat16 g_wf1T_h[DOUT*DOUT];
__device__ __nv_bfloat16 g_wf1T_l[DOUT*DOUT];
__device__ __nv_bfloat16 g_wf2T_h[DOUT*DOUT];
__device__ __nv_bfloat16 g_wf2T_l[DOUT*DOUT];
__device__ float g_bqkv[768];

// ---------------- small helpers ----------------
__device__ __forceinline__ unsigned pk2(float a, float b) {
    __nv_bfloat162 t = __floats2bfloat162_rn(a, b);
    return *(unsigned*)&t;
}
__device__ __forceinline__ float rndbf(float x) {
    return __bfloat162float(__float2bfloat16_rn(x));
}
__device__ __forceinline__ uint32_t smem_u32(const void* p) {
    uint32_t a;
    asm("{ .reg .u64 t; cvta.to.shared.u64 t, %1; cvt.u32.u64 %0, t; }" : "=r"(a) : "l"(p));
    return a;
}
__device__ __forceinline__ uint32_t swz(uint32_t x) { return x ^ ((x >> 3) & 0x70); }

__device__ __forceinline__ void ldsm4(uint32_t* r, uint32_t addr) {
    asm volatile("ldmatrix.sync.aligned.m8n8.x4.shared.b16 {%0,%1,%2,%3}, [%4];"
        : "=r"(r[0]), "=r"(r[1]), "=r"(r[2]), "=r"(r[3]) : "r"(addr));
}
__device__ __forceinline__ void mma16816(float* c, const uint32_t* a, uint32_t b0, uint32_t b1) {
    asm volatile("mma.sync.aligned.m16n8k16.row.col.f32.bf16.bf16.f32 "
        "{%0,%1,%2,%3}, {%4,%5,%6,%7}, {%8,%9}, {%0,%1,%2,%3};"
        : "+f"(c[0]), "+f"(c[1]), "+f"(c[2]), "+f"(c[3])
        : "r"(a[0]), "r"(a[1]), "r"(a[2]), "r"(a[3]), "r"(b0), "r"(b1));
}
#define CP16(dst, src) asm volatile("cp.async.cg.shared.global [%0], [%1], 16;" :: "r"(dst), "l"(src))
#define CP_COMMIT()    asm volatile("cp.async.commit_group;" ::: "memory")
#define CP_WAIT1()     asm volatile("cp.async.wait_group 1;" ::: "memory")

// ---------------- merged prep ----------------
// [0,128) pack | [128,4224) feat+ln1 | [4224,4248) WqkvT | [4248,4249) Wp2T
// [4249,4265) Wf1T | [4265,4281) Wf2T | [4281,4284) bias | [4284,4412) knn A/B rows
#define PREP_BLOCKS 4412

__device__ __forceinline__ void tileT(const float* __restrict__ W,
                                      __nv_bfloat16* Th, __nv_bfloat16* Tl,
                                      int Kd, int Nd, int k0, int n0,
                                      int tid, float (*ts)[65]) {
    #pragma unroll
    for (int i = 0; i < 16; ++i) {
        int e = tid + i*256;
        int r = e >> 6, c = e & 63;
        ts[r][c] = W[(size_t)(k0 + r) * Nd + n0 + c];
    }
    __syncthreads();
    #pragma unroll
    for (int i = 0; i < 16; ++i) {
        int e = tid + i*256;
        int kk = e & 63, nn = e >> 6;
        float x = ts[kk][nn];
        size_t o = (size_t)(n0 + nn) * Kd + k0 + kk;
        float hx = rndbf(x);
        Th[o] = __float2bfloat16_rn(x);
        if (Tl) Tl[o] = __float2bfloat16_rn(x - hx);
    }
}

__global__ void __launch_bounds__(256) k_prep(
    const float* __restrict__ xyz, const float* __restrict__ features,
    const float* __restrict__ Wq, const float* __restrict__ Wk, const float* __restrict__ Wv,
    const float* __restrict__ Wp2, const float* __restrict__ Wf1, const float* __restrict__ Wf2,
    const float* __restrict__ g1, const float* __restrict__ b1,
    const float* __restrict__ bq, const float* __restrict__ bk, const float* __restrict__ bv)
{
    __shared__ float ts[64][65];
    int bid = blockIdx.x, tid = threadIdx.x;
    if (bid < 128) {
        int i = bid * 256 + tid;
        float x = xyz[i*3+0], y = xyz[i*3+1], z = xyz[i*3+2];
        g_xyzw[i] = make_float4(x, y, z, x*x + y*y + z*z);
    } else if (bid < 4224) {
        int row = (bid - 128) * 8 + (tid >> 5);
        int lane = tid & 31;
        float4 v = ((const float4*)(features + (size_t)row * DIM))[lane];
        int idx = row*32 + lane;
        {
            float hx = rndbf(v.x), hy = rndbf(v.y), hz = rndbf(v.z), hw = rndbf(v.w);
            ((uint2*)g_feat_h)[idx] = make_uint2(pk2(v.x, v.y), pk2(v.z, v.w));
            ((uint2*)g_feat_l)[idx] = make_uint2(pk2(v.x-hx, v.y-hy), pk2(v.z-hz, v.w-hw));
        }
        float s = v.x + v.y + v.z + v.w;
        #pragma unroll
        for (int o = 16; o; o >>= 1) s += __shfl_xor_sync(~0u, s, o);
        float mu = s * (1.f/128.f);
        float dx = v.x-mu, dy = v.y-mu, dz = v.z-mu, dw = v.w-mu;
        float s2 = dx*dx + dy*dy + dz*dz + dw*dw;
        #pragma unroll
        for (int o = 16; o; o >>= 1) s2 += __shfl_xor_sync(~0u, s2, o);
        float rs = rsqrtf(s2 * (1.f/128.f) + 1e-5f);
        float4 gg = ((const float4*)g1)[lane];
        float4 bb = ((const float4*)b1)[lane];
        float rx = dx*rs*gg.x + bb.x, ry = dy*rs*gg.y + bb.y;
        float rz = dz*rs*gg.z + bb.z, rw = dw*rs*gg.w + bb.w;
        float hx = rndbf(rx), hy = rndbf(ry), hz = rndbf(rz), hw = rndbf(rw);
        ((uint2*)g_lnf_h)[idx] = make_uint2(pk2(rx, ry), pk2(rz, rw));
        ((uint2*)g_lnf_l)[idx] = make_uint2(pk2(rx-hx, ry-hy), pk2(rz-hz, rw-hw));
    } else if (bid < 4248) {
        int b2 = bid - 4224;
        int m = b2 >> 3, tt = b2 & 7;
        const float* W = m == 0 ? Wq : (m == 1 ? Wk : Wv);
        tileT(W, g_wqkvT_h + m*256*DIM, g_wqkvT_l + m*256*DIM,
              DIM, DOUT, (tt & 1)*64, (tt >> 1)*64, tid, ts);
    } else if (bid < 4249) {
        tileT(Wp2, g_wp2T_h, nullptr, HD, HD, 0, 0, tid, ts);
    } else if (bid < 4265) {
        int b2 = bid - 4249;
        tileT(Wf1, g_wf1T_h, g_wf1T_l, DOUT, DOUT, (b2 & 3)*64, (b2 >> 2)*64, tid, ts);
    } else if (bid < 4281) {
        int b2 = bid - 4265;
        tileT(Wf2, g_wf2T_h, g_wf2T_l, DOUT, DOUT, (b2 & 3)*64, (b2 >> 2)*64, tid, ts);
    } else if (bid < 4284) {
        int t = (bid - 4281) * 256 + tid;
        if (t < 256)      g_bqkv[t] = bq[t];
        else if (t < 512) g_bqkv[t] = bk[t-256];
        else              g_bqkv[t] = bv[t-512];
    } else {
        // build knn mma rows (3-term splits)
        int i = (bid - 4284) * 256 + tid;
        float x = xyz[i*3+0], y = xyz[i*3+1], z = xyz[i*3+2];
        float s = x*x + y*y + z*z;
        float x0 = rndbf(x), x1 = rndbf(x - x0), x2 = x - x0 - x1;
        float y0 = rndbf(y), y1 = rndbf(y - y0), y2 = y - y0 - y1;
        float z0 = rndbf(z), z1 = rndbf(z - z0), z2 = z - z0 - z1;
        float X = -2.f*x, Y = -2.f*y, Z = -2.f*z;
        float X0 = rndbf(X), X1 = rndbf(X - X0), X2 = X - X0 - X1;
        float Y0 = rndbf(Y), Y1 = rndbf(Y - Y0), Y2 = Y - Y0 - Y1;
        float Z0 = rndbf(Z), Z1 = rndbf(Z - Z0), Z2 = Z - Z0 - Z1;
        float s0 = rndbf(s), s1 = rndbf(s - s0), s2 = s - s0 - s1;
        unsigned ar[16], br[16];
        // A slots: x0 y0 z0 | x0 y0 z0 | x1 y1 z1 | x1 y1 z1 | x0 y0 z0 | x2 y2 z2 | 1 1 1 | 0..
        ar[0]=pk2(x0,y0);  ar[1]=pk2(z0,x0);  ar[2]=pk2(y0,z0);
        ar[3]=pk2(x1,y1);  ar[4]=pk2(z1,x1);  ar[5]=pk2(y1,z1);
        ar[6]=pk2(x0,y0);  ar[7]=pk2(z0,x2);  ar[8]=pk2(y2,z2);
        ar[9]=pk2(1.f,1.f); ar[10]=pk2(1.f,0.f);
        ar[11]=0; ar[12]=0; ar[13]=0; ar[14]=0; ar[15]=0;
        // B slots: X0 Y0 Z0 | X1 Y1 Z1 | X0 Y0 Z0 | X1 Y1 Z1 | X2 Y2 Z2 | X0 Y0 Z0 | s0 s1 s2 | 0..
        br[0]=pk2(X0,Y0);  br[1]=pk2(Z0,X1);  br[2]=pk2(Y1,Z1);
        br[3]=pk2(X0,Y0);  br[4]=pk2(Z0,X1);  br[5]=pk2(Y1,Z1);
        br[6]=pk2(X2,Y2);  br[7]=pk2(Z2,X0);  br[8]=pk2(Y0,Z0);
        br[9]=pk2(s0,s1);  br[10]=pk2(s2,0.f);
        br[11]=0; br[12]=0; br[13]=0; br[14]=0; br[15]=0;
        #pragma unroll
        for (int j = 0; j < 4; ++j) {
            *(uint4*)(g_kA + (size_t)i*32 + j*8) = *(uint4*)&ar[j*4];
            *(uint4*)(g_kB + (size_t)i*32 + j*8) = *(uint4*)&br[j*4];
        }
    }
}

// ---------------- threshold kernel (SIMT sampling, rank-16 bound) ----------------
__global__ void __launch_bounds__(512) k_thresh() {
    __shared__ float4 tile[2048];
    int t = threadIdx.x, lane = t & 31, w = t >> 5;
    int b = blockIdx.y;
    int q0 = blockIdx.x * 64 + w * 4;
    const float INF = 3.402823e38f;
    for (int i = t; i < 2048; i += 512)
        tile[i] = g_xyzw[b*NPTS + i];
    __syncthreads();
    float qx2[4], qy2[4], qz2[4];
    #pragma unroll
    for (int qq = 0; qq < 4; ++qq) {
        float4 me = g_xyzw[b*NPTS + q0 + qq];
        qx2[qq] = -2.f*me.x; qy2[qq] = -2.f*me.y; qz2[qq] = -2.f*me.z;
    }
    float mn[4] = {INF, INF, INF, INF};
    #pragma unroll 4
    for (int i = 0; i < 64; ++i) {
        float4 p = tile[i*32 + lane];
        #pragma unroll
        for (int qq = 0; qq < 4; ++qq) {
            float d = fmaf(qx2[qq],p.x,fmaf(qy2[qq],p.y,fmaf(qz2[qq],p.z,p.w)));
            mn[qq] = fminf(mn[qq], d);
        }
    }
    #pragma unroll
    for (int qq = 0; qq < 4; ++qq) {
        float v = mn[qq];
        #pragma unroll
        for (int k = 2; k <= 32; k <<= 1) {
            #pragma unroll
            for (int j = k >> 1; j > 0; j >>= 1) {
                float o = __shfl_xor_sync(~0u, v, j);
                bool up = ((lane & k) == 0);
                bool lower = ((lane & j) == 0);
                v = (lower == up) ? fminf(v, o) : fmaxf(v, o);
            }
        }
        float T = __shfl_sync(~0u, v, 15);
        if (lane == 0) g_T[b*NPTS + q0 + qq] = T + 1e-4f;
    }
}

// ---------------- MMA KNN: 64 queries x 8192 candidates per CTA ----------------
#define KM_CAP  256
#define KM_A    0
#define KM_B0   4096
#define KM_B1   8192
#define KM_LIST 12288
#define KM_CNT  (12288 + 64*KM_CAP*4)
#define SMEM_KM (KM_CNT + 256)

__global__ void __launch_bounds__(256) k_knnmma() {
    extern __shared__ char sm[];
    uint32_t smb = smem_u32(sm);
    int*      lists = (int*)(sm + KM_LIST);
    unsigned* cnt   = (unsigned*)(sm + KM_CNT);
    int t = threadIdx.x, lane = t & 31, w = t >> 5;
    int wm = w & 3, wn = w >> 2;
    int b = blockIdx.x >> 7;
    int qb = (blockIdx.x & 127) * 64;
    int gq0 = b*NPTS + qb;
    const float INF = 3.402823e38f;

    if (t < 64) cnt[t] = 0;
    {   // load A tile: 64 rows x 64B
        int row = t >> 2, seg = t & 3;
        *(uint4*)(sm + KM_A + row*64 + seg*16) = *(const uint4*)(g_kA + (size_t)(gq0+row)*32 + seg*8);
    }
    __syncthreads();

    uint32_t af[2][4];
    {
        uint32_t base = smb + KM_A + (uint32_t)(wm*16 + (lane & 15))*64 + (lane >> 4)*16;
        ldsm4(af[0], base);
        ldsm4(af[1], base + 32);
    }
    int q0l = wm*16 + (lane >> 2);
    float T0 = g_T[b*NPTS + qb + q0l];
    float T1 = g_T[b*NPTS + qb + q0l + 8];

    auto issueB = [&](int ch, int stg) {
        int row = t >> 2, seg = t & 3;
        const __nv_bfloat16* src = g_kB + (size_t)(b*NPTS + ch*64 + row)*32 + seg*8;
        CP16(smb + (stg ? KM_B1 : KM_B0) + row*64 + seg*16, src);
    };
    issueB(0, 0); CP_COMMIT();
    issueB(1, 1); CP_COMMIT();

    for (int ch = 0; ch < 128; ++ch) {
        CP_WAIT1();
        __syncthreads();
        uint32_t Bb = smb + ((ch & 1) ? KM_B1 : KM_B0);
        #pragma unroll
        for (int nb = 0; nb < 2; ++nb) {
            uint32_t bf0[4], bf1[4];
            uint32_t ro = Bb + (uint32_t)(wn*32 + nb*16 + (lane & 15))*64 + (lane >> 4)*16;
            ldsm4(bf0, ro);
            ldsm4(bf1, ro + 32);
            #pragma unroll
            for (int f = 0; f < 2; ++f) {
                float c4[4] = {0.f, 0.f, 0.f, 0.f};
                mma16816(c4, af[0], bf0[f], bf0[f+2]);
                mma16816(c4, af[1], bf1[f], bf1[f+2]);
                int cb = ch*64 + wn*32 + nb*16 + f*8 + (lane & 3)*2;
                if (c4[0] <= T0) { unsigned p = atomicAdd(&cnt[q0l], 1u);   if (p < KM_CAP) lists[q0l*KM_CAP + p] = cb; }
                if (c4[1] <= T0) { unsigned p = atomicAdd(&cnt[q0l], 1u);   if (p < KM_CAP) lists[q0l*KM_CAP + p] = cb + 1; }
                if (c4[2] <= T1) { unsigned p = atomicAdd(&cnt[q0l+8], 1u); if (p < KM_CAP) lists[(q0l+8)*KM_CAP + p] = cb; }
                if (c4[3] <= T1) { unsigned p = atomicAdd(&cnt[q0l+8], 1u); if (p < KM_CAP) lists[(q0l+8)*KM_CAP + p] = cb + 1; }
            }
        }
        __syncthreads();
        if (ch + 2 < 128) issueB(ch + 2, ch & 1);
        CP_COMMIT();
    }
    __syncthreads();
    if (t < 64 && cnt[t] > KM_CAP) cnt[t] = KM_CAP;
    __syncthreads();

    // selection: warp w handles queries w*8 .. w*8+7 (SIMT keys, R15 semantics)
    for (int qq = 0; qq < 8; ++qq) {
        int ql = w*8 + qq;
        int gq = gq0 + ql;
        float4 me = g_xyzw[gq];
        float qx2 = -2.f*me.x, qy2 = -2.f*me.y, qz2 = -2.f*me.z;
        int bs = (int)cnt[ql];
        float dd[8]; int ii[8];
        #pragma unroll
        for (int i = 0; i < 8; ++i) {
            int slot = lane + i*32;
            dd[i] = INF; ii[i] = 0x7fffffff;
            if (slot < bs) {
                int idx = lists[ql*KM_CAP + slot];
                float4 p = g_xyzw[b*NPTS + idx];
                dd[i] = fmaf(qx2,p.x,fmaf(qy2,p.y,fmaf(qz2,p.z,p.w)));
                ii[i] = idx;
            }
        }
        size_t ob = (size_t)gq * KNBR;
        for (int r = 0; r < KNBR; ++r) {
            float bk = dd[0]; int bi = ii[0];
            #pragma unroll
            for (int i = 1; i < 8; ++i)
                if (dd[i] < bk || (dd[i] == bk && ii[i] < bi)) { bk = dd[i]; bi = ii[i]; }
            #pragma unroll
            for (int o = 16; o; o >>= 1) {
                float ok = __shfl_xor_sync(~0u, bk, o);
                int   oi = __shfl_xor_sync(~0u, bi, o);
                if (ok < bk || (ok == bk && oi < bi)) { bk = ok; bi = oi; }
            }
            if (lane == 0) g_knn[ob + r] = bi;
            #pragma unroll
            for (int i = 0; i < 8; ++i)
                if (ii[i] == bi) { dd[i] = INF; ii[i] = 0x7fffffff; }
        }
    }
}

// ---------------- mma GEMM (unchanged R13/R15) ----------------
#define MG_STGB  24576
#define MG_SMEM  (2*MG_STGB)

__global__ void __launch_bounds__(256, 2) k_mgemm(
    const __nv_bfloat16* __restrict__ Ah, const __nv_bfloat16* __restrict__ Al,
    const __nv_bfloat16* __restrict__ Bh, const __nv_bfloat16* __restrict__ Bl,
    const float* __restrict__ bias,
    float* Cf, __nv_bfloat16* Ch, __nv_bfloat16* Cl,
    int K, int ldc, int relu, int kvmode)
{
    extern __shared__ char sm[];
    uint32_t smb = smem_u32(sm);
    int t = threadIdx.x, lane = t & 31, w = t >> 5;
    int wm = w & 3, wn = w >> 2;
    int c0 = blockIdx.y * 64;
    int r0 = blockIdx.x * 128;
    int nch = K >> 5;

    float acc[2][4][4];
    #pragma unroll
    for (int i = 0; i < 2; ++i)
        #pragma unroll
        for (int j = 0; j < 4; ++j)
            #pragma unroll
            for (int e = 0; e < 4; ++e) acc[i][j][e] = 0.f;

    int lrow = lane & 15;
    int lcb  = (lane >> 4) * 16;

    auto issue = [&](int c, int stg) {
        int kc = c * 32;
        uint32_t Ab = smb + stg*MG_STGB;
        uint32_t Bb = Ab + 16384;
        #pragma unroll
        for (int i = 0; i < 4; ++i) {
            int e = t + i*256;
            int row = e >> 3, seg = e & 7;
            const __nv_bfloat16* src = (seg < 4 ? Ah : Al) + (size_t)(r0+row)*K + kc + (seg & 3)*8;
            CP16(Ab + swz((uint32_t)row*128 + seg*16), src);
        }
        #pragma unroll
        for (int i = 0; i < 2; ++i) {
            int e = t + i*256;
            int row = e >> 3, seg = e & 7;
            const __nv_bfloat16* src = (seg < 4 ? Bh : Bl) + (size_t)(c0+row)*K + kc + (seg & 3)*8;
            CP16(Bb + swz((uint32_t)row*128 + seg*16), src);
        }
    };

    issue(0, 0); CP_COMMIT();
    issue(1, 1); CP_COMMIT();

    for (int c = 0; c < nch; ++c) {
        CP_WAIT1();
        __syncthreads();
        uint32_t Ab = smb + (c & 1)*MG_STGB;
        uint32_t Bb = Ab + 16384;
        #pragma unroll
        for (int s = 0; s < 2; ++s) {
            int kb = s*32 + lcb;
            uint32_t ah[2][4], al[2][4];
            #pragma unroll
            for (int mb = 0; mb < 2; ++mb) {
                uint32_t ro = (uint32_t)(wm*32 + mb*16 + lrow)*128;
                ldsm4(ah[mb], Ab + swz(ro + kb));
                ldsm4(al[mb], Ab + swz(ro + 64 + kb));
            }
            #pragma unroll
            for (int nb = 0; nb < 2; ++nb) {
                uint32_t bh[4], bl[4];
                uint32_t ro = (uint32_t)(wn*32 + nb*16 + lrow)*128;
                ldsm4(bh, Bb + swz(ro + kb));
                ldsm4(bl, Bb + swz(ro + 64 + kb));
                #pragma unroll
                for (int mb = 0; mb < 2; ++mb) {
                    float* cA = acc[mb][nb*2];
                    float* cB = acc[mb][nb*2+1];
                    mma16816(cA, ah[mb], bh[0], bh[2]);
                    mma16816(cB, ah[mb], bh[1], bh[3]);
                    mma16816(cA, ah[mb], bl[0], bl[2]);
                    mma16816(cB, ah[mb], bl[1], bl[3]);
                    mma16816(cA, al[mb], bh[0], bh[2]);
                    mma16816(cB, al[mb], bh[1], bh[3]);
                }
            }
        }
        __syncthreads();
        if (c + 2 < nch) issue(c + 2, c & 1);
        CP_COMMIT();
    }

    int rbase = r0 + wm*32 + (lane >> 2);
    int cb = c0 + wn*32 + (lane & 3)*2;
    #pragma unroll
    for (int mb = 0; mb < 2; ++mb) {
        #pragma unroll
        for (int nn = 0; nn < 4; ++nn) {
            int col = cb + nn*8;
            float b0 = bias[col], b1 = bias[col+1];
            float v0 = acc[mb][nn][0] + b0, v1 = acc[mb][nn][1] + b1;
            float v2 = acc[mb][nn][2] + b0, v3 = acc[mb][nn][3] + b1;
            if (relu) {
                v0 = fmaxf(v0, 0.f); v1 = fmaxf(v1, 0.f);
                v2 = fmaxf(v2, 0.f); v3 = fmaxf(v3, 0.f);
            }
            int ra_row = rbase + mb*16, rb_row = rbase + mb*16 + 8;
            if (kvmode) {
                if (c0 < 256) {
                    *(float2*)(g_qf + (size_t)ra_row * DOUT + col) = make_float2(v0, v1);
                    *(float2*)(g_qf + (size_t)rb_row * DOUT + col) = make_float2(v2, v3);
                } else if (c0 < 512) {
                    int kc2 = col - 256;
                    *(unsigned*)(g_kvb + (size_t)ra_row * DOUT + kc2) = pk2(v0, v1);
                    *(unsigned*)(g_kvb + (size_t)rb_row * DOUT + kc2) = pk2(v2, v3);
                } else {
                    int vc2 = col - 512;
                    *(float2*)(g_vf + (size_t)ra_row * DOUT + vc2) = make_float2(v0, v1);
                    *(float2*)(g_vf + (size_t)rb_row * DOUT + vc2) = make_float2(v2, v3);
                }
            } else {
                size_t ra = (size_t)ra_row * ldc + col;
                size_t rb = (size_t)rb_row * ldc + col;
                if (Cf) {
                    *(float2*)(Cf + ra) = make_float2(v0, v1);
                    *(float2*)(Cf + rb) = make_float2(v2, v3);
                }
                if (Ch) {
                    float h0 = rndbf(v0), h1 = rndbf(v1), h2 = rndbf(v2), h3 = rndbf(v3);
                    *(unsigned*)(Ch + ra) = pk2(v0, v1);
                    *(unsigned*)(Cl + ra) = pk2(v0-h0, v1-h1);
                    *(unsigned*)(Ch + rb) = pk2(v2, v3);
                    *(unsigned*)(Cl + rb) = pk2(v2-h2, v3-h3);
                }
            }
        }
    }
}

// ---------------- fused pos GEMM ----------------
#define PG_A 0
#define PG_B 16384
#define PG_W 24576
#define SMEM_PG (24576 + 1024)

__global__ void __launch_bounds__(256) k_pgemm(
    const float* __restrict__ Wp1, const float* __restrict__ bp1,
    const float* __restrict__ bias)
{
    extern __shared__ char sm[];
    uint32_t smb = smem_u32(sm);
    float* ws = (float*)(sm + PG_W);
    int t = threadIdx.x, lane = t & 31, w = t >> 5;
    int wm = w & 3, wn = w >> 2;
    int r0 = blockIdx.x * 128;

    if (t < 192) ws[t] = Wp1[t];
    else ws[t] = bp1[t - 192];
    #pragma unroll 2
    for (int e = t; e < 512; e += 256) {
        int row = e >> 3, vo = e & 7;
        *(uint4*)(sm + PG_B + swz(row*128 + vo*16)) = *(const uint4*)(g_wp2T_h + row*64 + vo*8);
    }
    __syncthreads();

    {
        int row = t >> 1, ch = t & 1;
        int rr = r0 + row;
        int b = rr >> 17, n = (rr >> 4) & (NPTS - 1);
        int idx = g_knn[rr];
        float4 nbp = g_xyzw[(b << 13) + idx];
        float4 ctp = g_xyzw[(b << 13) + n];
        float rx = nbp.x - ctp.x, ry = nbp.y - ctp.y, rz = nbp.z - ctp.z;
        uint32_t hp[16];
        #pragma unroll
        for (int cc = 0; cc < 32; cc += 2) {
            int c = ch*32 + cc;
            float v0 = fmaf(rx, ws[c],   fmaf(ry, ws[64+c],   fmaf(rz, ws[128+c],   ws[192+c])));
            float v1 = fmaf(rx, ws[c+1], fmaf(ry, ws[64+c+1], fmaf(rz, ws[128+c+1], ws[192+c+1])));
            hp[cc>>1] = pk2(fmaxf(v0, 0.f), fmaxf(v1, 0.f));
        }
        uint32_t rbyte = (uint32_t)row*128 + ch*64;
        #pragma unroll
        for (int i = 0; i < 4; ++i)
            *(uint4*)(sm + PG_A + swz(rbyte + i*16)) = *(uint4*)&hp[i*4];
    }
    __syncthreads();

    float acc[2][4][4];
    #pragma unroll
    for (int i = 0; i < 2; ++i)
        #pragma unroll
        for (int j = 0; j < 4; ++j)
            #pragma unroll
            for (int e = 0; e < 4; ++e) acc[i][j][e] = 0.f;
    int lrow = lane & 15, lcolb = (lane >> 4) * 16;
    #pragma unroll
    for (int s = 0; s < 4; ++s) {
        int kb = s*32 + lcolb;
        uint32_t ah[2][4];
        #pragma unroll
        for (int mb = 0; mb < 2; ++mb)
            ldsm4(ah[mb], smb + PG_A + swz((uint32_t)(wm*32 + mb*16 + lrow)*128 + kb));
        #pragma unroll
        for (int nb = 0; nb < 2; ++nb) {
            uint32_t bh[4];
            ldsm4(bh, smb + PG_B + swz((uint32_t)(wn*32 + nb*16 + lrow)*128 + kb));
            #pragma unroll
            for (int mb = 0; mb < 2; ++mb) {
                mma16816(acc[mb][nb*2],   ah[mb], bh[0], bh[2]);
                mma16816(acc[mb][nb*2+1], ah[mb], bh[1], bh[3]);
            }
        }
    }

    int rbase = r0 + wm*32 + (lane >> 2);
    int cb = wn*32 + (lane & 3)*2;
    #pragma unroll
    for (int mb = 0; mb < 2; ++mb) {
        #pragma unroll
        for (int nn = 0; nn < 4; ++nn) {
            int col = cb + nn*8;
            float b0 = bias[col], b1 = bias[col+1];
            size_t ra = (size_t)(rbase + mb*16) * HD + col;
            size_t rb = (size_t)(rbase + mb*16 + 8) * HD + col;
            *(unsigned*)(g_posb + ra) = pk2(acc[mb][nn][0] + b0, acc[mb][nn][1] + b1);
            *(unsigned*)(g_posb + rb) = pk2(acc[mb][nn][2] + b0, acc[mb][nn][3] + b1);
        }
    }
}

// ---------------- fused attention (R13 config) ----------------
__global__ void __launch_bounds__(128) k_attn(float* __restrict__ attn_out) {
    __shared__ int   idx_s[16];
    __shared__ float pos_s[16][68];
    __shared__ float k_s[16][260];
    __shared__ float q_s[256];
    __shared__ float logit_s[64];
    __shared__ float attn_s[64];
    int t  = threadIdx.x;
    int gp = blockIdx.x;
    int b  = gp >> 13, n = gp & (NPTS-1);

    if (t < 16) idx_s[t] = g_knn[gp*KNBR + t];
    if (t < 64) ((float4*)q_s)[t] = ((const float4*)(g_qf + (size_t)gp * DOUT))[t];
    {
        const uint2* ps = (const uint2*)(g_posb + (size_t)gp * KNBR * HD);
        #pragma unroll
        for (int e = t; e < 256; e += 128) {
            int jj = e >> 4, cc = e & 15;
            uint2 u = ps[e];
            float2 f0 = __bfloat1622float2(*(__nv_bfloat162*)&u.x);
            float2 f1 = __bfloat1622float2(*(__nv_bfloat162*)&u.y);
            *(float4*)&pos_s[jj][cc*4] = make_float4(f0.x, f0.y, f1.x, f1.y);
        }
    }
    __syncthreads();
    #pragma unroll
    for (int e = t; e < 1024; e += 128) {
        int jj = e >> 6, uu = e & 63;
        size_t rowb = ((size_t)b * NPTS + idx_s[jj]) * DOUT;
        uint2 u = ((const uint2*)(g_kvb + rowb))[uu];
        float2 f0 = __bfloat1622float2(*(__nv_bfloat162*)&u.x);
        float2 f1 = __bfloat1622float2(*(__nv_bfloat162*)&u.y);
        *(float4*)&k_s[jj][uu*4] = make_float4(f0.x, f0.y, f1.x, f1.y);
    }
    __syncthreads();
    {
        int p = t >> 1, half = t & 1;
        int jj = p & 15, h = p >> 4;
        float s = 0.f;
        int cbs = half * 32;
        #pragma unroll
        for (int c = 0; c < 32; ++c) {
            int cc = cbs + c;
            s = fmaf(q_s[h*64+cc], k_s[jj][h*64+cc] + pos_s[jj][cc], s);
        }
        s += __shfl_xor_sync(~0u, s, 1);
        if (half == 0) logit_s[h*16 + jj] = s * 0.125f;
    }
    __syncthreads();
    if (t < 64) {
        int h2 = t >> 4, j2 = t & 15;
        float l = logit_s[t];
        float mx = l;
        #pragma unroll
        for (int o = 8; o; o >>= 1) mx = fmaxf(mx, __shfl_xor_sync(~0u, mx, o));
        float ex = expf(l - mx);
        float sum = ex;
        #pragma unroll
        for (int o = 8; o; o >>= 1) sum += __shfl_xor_sync(~0u, sum, o);
        float a = ex / sum;
        attn_s[t] = a;
        attn_out[(((size_t)b*NH + h2) * NPTS + n) * KNBR + j2] = a;
    }
    __syncthreads();
    #pragma unroll
    for (int ee = 0; ee < 2; ++ee) {
        int e = t + ee*128;
        int h3 = e >> 6, c = e & 63;
        float s = 0.f;
        #pragma unroll
        for (int j = 0; j < 16; ++j) {
            float v = g_vf[((size_t)b * NPTS + idx_s[j]) * DOUT + e];
            s = fmaf(attn_s[h3*16 + j], v + pos_s[j][c], s);
        }
        float hs = rndbf(s);
        g_mid_h[(size_t)gp * DOUT + e] = __float2bfloat16_rn(s);
        g_mid_l[(size_t)gp * DOUT + e] = __float2bfloat16_rn(s - hs);
    }
}

// ---------------- final ----------------
__global__ void k_final(const float* __restrict__ g2, const float* __restrict__ b2,
                        float* __restrict__ out) {
    int warp = (blockIdx.x * blockDim.x + threadIdx.x) >> 5;
    int lane = threadIdx.x & 31;
    const float4* row = (const float4*)(g_fc2 + (size_t)warp * DOUT);
    float4 v0 = row[lane*2], v1 = row[lane*2+1];
    float s = v0.x+v0.y+v0.z+v0.w + v1.x+v1.y+v1.z+v1.w;
    #pragma unroll
    for (int o = 16; o; o >>= 1) s += __shfl_xor_sync(~0u, s, o);
    float mu = s * (1.f/256.f);
    float d0x=v0.x-mu, d0y=v0.y-mu, d0z=v0.z-mu, d0w=v0.w-mu;
    float d1x=v1.x-mu, d1y=v1.y-mu, d1z=v1.z-mu, d1w=v1.w-mu;
    float s2 = d0x*d0x+d0y*d0y+d0z*d0z+d0w*d0w + d1x*d1x+d1y*d1y+d1z*d1z+d1w*d1w;
    #pragma unroll
    for (int o = 16; o; o >>= 1) s2 += __shfl_xor_sync(~0u, s2, o);
    float rs = rsqrtf(s2 * (1.f/256.f) + 1e-5f);
    float4 gA = ((const float4*)g2)[lane*2],  gB = ((const float4*)g2)[lane*2+1];
    float4 bA = ((const float4*)b2)[lane*2],  bB = ((const float4*)b2)[lane*2+1];
    const float4* lq = (const float4*)(g_lnq + (size_t)warp * DOUT);
    float4 qA = lq[lane*2], qB = lq[lane*2+1];
    float4 oA, oB;
    oA.x = d0x*rs*gA.x + bA.x + qA.x; oA.y = d0y*rs*gA.y + bA.y + qA.y;
    oA.z = d0z*rs*gA.z + bA.z + qA.z; oA.w = d0w*rs*gA.w + bA.w + qA.w;
    oB.x = d1x*rs*gB.x + bB.x + qB.x; oB.y = d1y*rs*gB.y + bB.y + qB.y;
    oB.z = d1z*rs*gB.z + bB.z + qB.z; oB.w = d1w*rs*gB.w + bB.w + qB.w;
    float4* dst = (float4*)(out + (size_t)warp * DOUT);
    dst[lane*2]   = oA;
    dst[lane*2+1] = oB;
}

// ---------------- host launcher ----------------
extern "C" void kernel_launch(void* const* d_in, const int* in_sizes, int n_in,
                              void* d_out, int out_size) {
    const float* xyz      = (const float*)d_in[0];
    const float* features = (const float*)d_in[1];
    const float* Wq  = (const float*)d_in[2];
    const float* bq  = (const float*)d_in[3];
    const float* Wk  = (const float*)d_in[4];
    const float* bk  = (const float*)d_in[5];
    const float* Wv  = (const float*)d_in[6];
    const float* bv  = (const float*)d_in[7];
    const float* Wp1 = (const float*)d_in[8];
    const float* bp1 = (const float*)d_in[9];
    const float* Wp2 = (const float*)d_in[10];
    const float* bp2 = (const float*)d_in[11];
    const float* Wf1 = (const float*)d_in[12];
    const float* bf1 = (const float*)d_in[13];
    const float* Wf2 = (const float*)d_in[14];
    const float* bf2 = (const float*)d_in[15];
    const float* g1  = (const float*)d_in[16];
    const float* b1  = (const float*)d_in[17];
    const float* g2  = (const float*)d_in[18];
    const float* b2  = (const float*)d_in[19];

    float* out      = (float*)d_out;
    float* attn_out = out + (size_t)ROWS * DOUT;

    #define SYM(p, s) float* p; cudaGetSymbolAddress((void**)&p, s)
    #define SYMB(p, s) __nv_bfloat16* p; cudaGetSymbolAddress((void**)&p, s)
    SYMB(p_feat_h, g_feat_h); SYMB(p_feat_l, g_feat_l);
    SYMB(p_lnf_h,  g_lnf_h);  SYMB(p_lnf_l,  g_lnf_l);
    SYM(p_lnq, g_lnq); SYM(p_fc2, g_fc2);
    SYMB(p_mid_h, g_mid_h); SYMB(p_mid_l, g_mid_l);
    SYMB(p_fc1_h, g_fc1_h); SYMB(p_fc1_l, g_fc1_l);
    SYMB(p_wqkvT_h, g_wqkvT_h); SYMB(p_wqkvT_l, g_wqkvT_l);
    SYMB(p_wf1T_h, g_wf1T_h);   SYMB(p_wf1T_l, g_wf1T_l);
    SYMB(p_wf2T_h, g_wf2T_h);   SYMB(p_wf2T_l, g_wf2T_l);
    SYM(p_bqkv, g_bqkv);

    static cudaStream_t s2 = nullptr, s3 = nullptr;
    static cudaEvent_t evPrep = nullptr, evSide = nullptr, evLnq = nullptr;
    static bool attr_done = false;
    if (!attr_done) {
        cudaFuncSetAttribute(k_mgemm,  cudaFuncAttributeMaxDynamicSharedMemorySize, MG_SMEM);
        cudaFuncSetAttribute(k_knnmma, cudaFuncAttributeMaxDynamicSharedMemorySize, SMEM_KM);
        cudaFuncSetAttribute(k_pgemm,  cudaFuncAttributeMaxDynamicSharedMemorySize, SMEM_PG);
        cudaStreamCreateWithFlags(&s2, cudaStreamNonBlocking);
        cudaStreamCreateWithFlags(&s3, cudaStreamNonBlocking);
        cudaEventCreateWithFlags(&evPrep, cudaEventDisableTiming);
        cudaEventCreateWithFlags(&evSide, cudaEventDisableTiming);
        cudaEventCreateWithFlags(&evLnq, cudaEventDisableTiming);
        attr_done = true;
    }

    // 1: merged prep (main)
    k_prep<<<PREP_BLOCKS, 256>>>(xyz, features, Wq, Wk, Wv, Wp2, Wf1, Wf2, g1, b1, bq, bk, bv);
    cudaEventRecord(evPrep, 0);

    // 2: qkv GEMM (main)
    {
        dim3 g(ROWS/128, 12);
        k_mgemm<<<g, 256, MG_SMEM>>>(p_feat_h, p_feat_l, p_wqkvT_h, p_wqkvT_l,
                                     p_bqkv, nullptr, nullptr, nullptr, DIM, 768, 0, 1);
    }

    // 3: threshold (s2)
    cudaStreamWaitEvent(s2, evPrep, 0);
    {
        dim3 tg(NPTS/64, BATCH);
        k_thresh<<<tg, 512, 0, s2>>>();
    }
    // 4: mma knn (s2)  <- profiler slot
    k_knnmma<<<512, 256, SMEM_KM, s2>>>();
    // 5: pos (s2)
    k_pgemm<<<NROWS/128, 256, SMEM_PG, s2>>>(Wp1, bp1, bp2);
    cudaEventRecord(evSide, s2);

    // 6: lnq GEMM (s3)
    cudaStreamWaitEvent(s3, evPrep, 0);
    {
        dim3 g(ROWS/128, 4);
        k_mgemm<<<g, 256, MG_SMEM, s3>>>(p_lnf_h, p_lnf_l, p_wqkvT_h, p_wqkvT_l,
                                         bq, p_lnq, nullptr, nullptr, DIM, DOUT, 0, 0);
    }
    cudaEventRecord(evLnq, s3);

    // join, then attention
    cudaStreamWaitEvent(0, evSide, 0);
    k_attn<<<ROWS, 128>>>(attn_out);

    // fc1, fc2
    {
        dim3 g(ROWS/128, 4);
        k_mgemm<<<g, 256, MG_SMEM>>>(p_mid_h, p_mid_l, p_wf1T_h, p_wf1T_l,
                                     bf1, nullptr, p_fc1_h, p_fc1_l, DOUT, DOUT, 1, 0);
        k_mgemm<<<g, 256, MG_SMEM>>>(p_fc1_h, p_fc1_l, p_wf2T_h, p_wf2T_l,
                                     bf2, p_fc2, nullptr, nullptr, DOUT, DOUT, 0, 0);
    }

    // final (needs lnq)
    cudaStreamWaitEvent(0, evLnq, 0);
    k_final<<<ROWS/8, 256>>>(g2, b2, out);
}

// round 17
// speedup vs baseline: 1.9158x; 1.9158x over previous
#include <cuda_runtime.h>
#include <cuda_bf16.h>
#include <cstdint>
#include <math.h>

#define BATCH 4
#define NPTS  8192
#define DIM   128
#define DOUT  256
#define NH    4
#define HD    64
#define KNBR  16
#define ROWS  (BATCH*NPTS)          // 32768
#define NROWS (BATCH*NPTS*KNBR)     // 524288

// ---------------- scratch ----------------
__device__ float4 g_xyzw[ROWS];
__device__ int    g_knn[NROWS];
__device__ __nv_bfloat16 g_feat_h[ROWS*DIM];
__device__ __nv_bfloat16 g_feat_l[ROWS*DIM];
__device__ __nv_bfloat16 g_lnf_h[ROWS*DIM];
__device__ __nv_bfloat16 g_lnf_l[ROWS*DIM];
__device__ float  g_qf[(size_t)ROWS*DOUT];
__device__ __nv_bfloat16 g_kvb[(size_t)ROWS*DOUT];
__device__ float  g_vf[(size_t)ROWS*DOUT];
__device__ float  g_lnq[ROWS*DOUT];
__device__ __nv_bfloat16 g_posb[(size_t)NROWS*HD];
__device__ __nv_bfloat16 g_mid_h[ROWS*DOUT];
__device__ __nv_bfloat16 g_mid_l[ROWS*DOUT];
__device__ __nv_bfloat16 g_fc1_h[ROWS*DOUT];
__device__ __nv_bfloat16 g_fc1_l[ROWS*DOUT];
__device__ float  g_fc2[ROWS*DOUT];
__device__ __nv_bfloat16 g_wqkvT_h[768*DIM];
__device__ __nv_bfloat16 g_wqkvT_l[768*DIM];
__device__ __nv_bfloat16 g_wp2T_h[HD*HD];
__device__ __nv_bfloat16 g_wf1T_h[DOUT*DOUT];
__device__ __nv_bfloat16 g_wf1T_l[DOUT*DOUT];
__device__ __nv_bfloat16 g_wf2T_h[DOUT*DOUT];
__device__ __nv_bfloat16 g_wf2T_l[DOUT*DOUT];
__device__ float g_bqkv[768];

// ---------------- small helpers ----------------
__device__ __forceinline__ unsigned pk2(float a, float b) {
    __nv_bfloat162 t = __floats2bfloat162_rn(a, b);
    return *(unsigned*)&t;
}
__device__ __forceinline__ float rndbf(float x) {
    return __bfloat162float(__float2bfloat16_rn(x));
}
__device__ __forceinline__ uint32_t smem_u32(const void* p) {
    uint32_t a;
    asm("{ .reg .u64 t; cvta.to.shared.u64 t, %1; cvt.u32.u64 %0, t; }" : "=r"(a) : "l"(p));
    return a;
}
__device__ __forceinline__ uint32_t swz(uint32_t x) { return x ^ ((x >> 3) & 0x70); }

__device__ __forceinline__ void ldsm4(uint32_t* r, uint32_t addr) {
    asm volatile("ldmatrix.sync.aligned.m8n8.x4.shared.b16 {%0,%1,%2,%3}, [%4];"
        : "=r"(r[0]), "=r"(r[1]), "=r"(r[2]), "=r"(r[3]) : "r"(addr));
}
__device__ __forceinline__ void mma16816(float* c, const uint32_t* a, uint32_t b0, uint32_t b1) {
    asm volatile("mma.sync.aligned.m16n8k16.row.col.f32.bf16.bf16.f32 "
        "{%0,%1,%2,%3}, {%4,%5,%6,%7}, {%8,%9}, {%0,%1,%2,%3};"
        : "+f"(c[0]), "+f"(c[1]), "+f"(c[2]), "+f"(c[3])
        : "r"(a[0]), "r"(a[1]), "r"(a[2]), "r"(a[3]), "r"(b0), "r"(b1));
}
#define CP16(dst, src) asm volatile("cp.async.cg.shared.global [%0], [%1], 16;" :: "r"(dst), "l"(src))
#define CP_COMMIT()    asm volatile("cp.async.commit_group;" ::: "memory")
#define CP_WAIT1()     asm volatile("cp.async.wait_group 1;" ::: "memory")

// ---------------- pack xyz (separate so knn can start early) ----------------
__global__ void k_pack(const float* __restrict__ xyz) {
    int i = blockIdx.x * 256 + threadIdx.x;
    float x = xyz[i*3+0], y = xyz[i*3+1], z = xyz[i*3+2];
    g_xyzw[i] = make_float4(x, y, z, x*x + y*y + z*z);
}

// ---------------- merged prep (no pack) ----------------
// [0,4096) feat+ln1 | [4096,4120) WqkvT | [4120,4121) Wp2T
// [4121,4137) Wf1T | [4137,4153) Wf2T | [4153,4156) bias
#define PREP_BLOCKS 4156

__device__ __forceinline__ void tileT(const float* __restrict__ W,
                                      __nv_bfloat16* Th, __nv_bfloat16* Tl,
                                      int Kd, int Nd, int k0, int n0,
                                      int tid, float (*ts)[65]) {
    #pragma unroll
    for (int i = 0; i < 16; ++i) {
        int e = tid + i*256;
        int r = e >> 6, c = e & 63;
        ts[r][c] = W[(size_t)(k0 + r) * Nd + n0 + c];
    }
    __syncthreads();
    #pragma unroll
    for (int i = 0; i < 16; ++i) {
        int e = tid + i*256;
        int kk = e & 63, nn = e >> 6;
        float x = ts[kk][nn];
        size_t o = (size_t)(n0 + nn) * Kd + k0 + kk;
        float hx = rndbf(x);
        Th[o] = __float2bfloat16_rn(x);
        if (Tl) Tl[o] = __float2bfloat16_rn(x - hx);
    }
}

__global__ void __launch_bounds__(256) k_prep(
    const float* __restrict__ features,
    const float* __restrict__ Wq, const float* __restrict__ Wk, const float* __restrict__ Wv,
    const float* __restrict__ Wp2, const float* __restrict__ Wf1, const float* __restrict__ Wf2,
    const float* __restrict__ g1, const float* __restrict__ b1,
    const float* __restrict__ bq, const float* __restrict__ bk, const float* __restrict__ bv)
{
    __shared__ float ts[64][65];
    int bid = blockIdx.x, tid = threadIdx.x;
    if (bid < 4096) {
        int row = bid * 8 + (tid >> 5);
        int lane = tid & 31;
        float4 v = ((const float4*)(features + (size_t)row * DIM))[lane];
        int idx = row*32 + lane;
        {
            float hx = rndbf(v.x), hy = rndbf(v.y), hz = rndbf(v.z), hw = rndbf(v.w);
            ((uint2*)g_feat_h)[idx] = make_uint2(pk2(v.x, v.y), pk2(v.z, v.w));
            ((uint2*)g_feat_l)[idx] = make_uint2(pk2(v.x-hx, v.y-hy), pk2(v.z-hz, v.w-hw));
        }
        float s = v.x + v.y + v.z + v.w;
        #pragma unroll
        for (int o = 16; o; o >>= 1) s += __shfl_xor_sync(~0u, s, o);
        float mu = s * (1.f/128.f);
        float dx = v.x-mu, dy = v.y-mu, dz = v.z-mu, dw = v.w-mu;
        float s2 = dx*dx + dy*dy + dz*dz + dw*dw;
        #pragma unroll
        for (int o = 16; o; o >>= 1) s2 += __shfl_xor_sync(~0u, s2, o);
        float rs = rsqrtf(s2 * (1.f/128.f) + 1e-5f);
        float4 gg = ((const float4*)g1)[lane];
        float4 bb = ((const float4*)b1)[lane];
        float rx = dx*rs*gg.x + bb.x, ry = dy*rs*gg.y + bb.y;
        float rz = dz*rs*gg.z + bb.z, rw = dw*rs*gg.w + bb.w;
        float hx = rndbf(rx), hy = rndbf(ry), hz = rndbf(rz), hw = rndbf(rw);
        ((uint2*)g_lnf_h)[idx] = make_uint2(pk2(rx, ry), pk2(rz, rw));
        ((uint2*)g_lnf_l)[idx] = make_uint2(pk2(rx-hx, ry-hy), pk2(rz-hz, rw-hw));
    } else if (bid < 4120) {
        int b2 = bid - 4096;
        int m = b2 >> 3, tt = b2 & 7;
        const float* W = m == 0 ? Wq : (m == 1 ? Wk : Wv);
        tileT(W, g_wqkvT_h + m*256*DIM, g_wqkvT_l + m*256*DIM,
              DIM, DOUT, (tt & 1)*64, (tt >> 1)*64, tid, ts);
    } else if (bid < 4121) {
        tileT(Wp2, g_wp2T_h, nullptr, HD, HD, 0, 0, tid, ts);
    } else if (bid < 4137) {
        int b2 = bid - 4121;
        tileT(Wf1, g_wf1T_h, g_wf1T_l, DOUT, DOUT, (b2 & 3)*64, (b2 >> 2)*64, tid, ts);
    } else if (bid < 4153) {
        int b2 = bid - 4137;
        tileT(Wf2, g_wf2T_h, g_wf2T_l, DOUT, DOUT, (b2 & 3)*64, (b2 >> 2)*64, tid, ts);
    } else {
        int t = (bid - 4153) * 256 + tid;
        if (t < 256)      g_bqkv[t] = bq[t];
        else if (t < 512) g_bqkv[t] = bk[t-256];
        else              g_bqkv[t] = bv[t-512];
    }
}

// ---------------- KNN: Q=4, atomic rare-hit compaction, reg-resident select ----------------
#define KNN_CAP 256
#define SMEM_KNN (32768 + 64*KNN_CAP*4 + 256)

__global__ void __launch_bounds__(512) k_knn2() {
    extern __shared__ char sk[];
    float4*   tile = (float4*)sk;
    int*      buf  = (int*)(sk + 32768);
    unsigned* cnt  = (unsigned*)(sk + 32768 + 64*KNN_CAP*4);
    int t = threadIdx.x, lane = t & 31, w = t >> 5;
    int b = blockIdx.y;
    int q0 = blockIdx.x * 64 + w * 4;
    const float INF = 3.402823e38f;

    if (t < 64) cnt[t] = 0;

    float qx2[4], qy2[4], qz2[4], T[4];
    #pragma unroll
    for (int qq = 0; qq < 4; ++qq) {
        float4 me = g_xyzw[b*NPTS + q0 + qq];
        qx2[qq] = -2.f*me.x; qy2[qq] = -2.f*me.y; qz2[qq] = -2.f*me.z;
    }

    for (int ti = 0; ti < 4; ++ti) {
        __syncthreads();
        for (int i = t; i < 2048; i += 512)
            tile[i] = g_xyzw[b*NPTS + ti*2048 + i];
        __syncthreads();

        if (ti == 0) {
            float mn[4] = {INF, INF, INF, INF};
            #pragma unroll 4
            for (int i = 0; i < 64; ++i) {
                float4 p = tile[i*32 + lane];
                #pragma unroll
                for (int qq = 0; qq < 4; ++qq) {
                    float d = fmaf(qx2[qq],p.x,fmaf(qy2[qq],p.y,fmaf(qz2[qq],p.z,p.w)));
                    mn[qq] = fminf(mn[qq], d);
                }
            }
            #pragma unroll
            for (int qq = 0; qq < 4; ++qq) {
                float v = mn[qq];
                #pragma unroll
                for (int k = 2; k <= 32; k <<= 1) {
                    #pragma unroll
                    for (int j = k >> 1; j > 0; j >>= 1) {
                        float o = __shfl_xor_sync(~0u, v, j);
                        bool up = ((lane & k) == 0);
                        bool lower = ((lane & j) == 0);
                        v = (lower == up) ? fminf(v, o) : fmaxf(v, o);
                    }
                }
                T[qq] = __shfl_sync(~0u, v, 15);
            }
        }

        // scan: rare-hit atomic compaction (no per-column ballot bookkeeping)
        #pragma unroll 4
        for (int c = 0; c < 64; ++c) {
            float4 p = tile[c*32 + lane];
            int cid = ti*2048 + c*32 + lane;
            #pragma unroll
            for (int qq = 0; qq < 4; ++qq) {
                float d = fmaf(qx2[qq],p.x,fmaf(qy2[qq],p.y,fmaf(qz2[qq],p.z,p.w)));
                if (d <= T[qq]) {
                    unsigned pos = atomicAdd(&cnt[w*4 + qq], 1u);
                    if (pos < KNN_CAP) buf[(w*4 + qq)*KNN_CAP + pos] = cid;
                }
            }
        }
    }
    __syncwarp();   // cnt/buf for (w,qq) written only by warp w

    // register-resident top-16 per query (lexicographic (d, idx))
    for (int qq = 0; qq < 4; ++qq) {
        int bs = (int)cnt[w*4 + qq];
        if (bs > KNN_CAP) bs = KNN_CAP;
        const int* bq_ = buf + (w*4 + qq)*KNN_CAP;
        float dd[8]; int ii[8];
        #pragma unroll
        for (int i = 0; i < 8; ++i) {
            int slot = lane + i*32;
            dd[i] = INF; ii[i] = 0x7fffffff;
            if (slot < bs) {
                int idx = bq_[slot];
                float4 p = g_xyzw[b*NPTS + idx];
                dd[i] = fmaf(qx2[qq],p.x,fmaf(qy2[qq],p.y,fmaf(qz2[qq],p.z,p.w)));
                ii[i] = idx;
            }
        }
        size_t ob = ((size_t)b*NPTS + q0 + qq) * KNBR;
        for (int r = 0; r < KNBR; ++r) {
            float bk = dd[0]; int bi = ii[0];
            #pragma unroll
            for (int i = 1; i < 8; ++i)
                if (dd[i] < bk || (dd[i] == bk && ii[i] < bi)) { bk = dd[i]; bi = ii[i]; }
            #pragma unroll
            for (int o = 16; o; o >>= 1) {
                float ok = __shfl_xor_sync(~0u, bk, o);
                int   oi = __shfl_xor_sync(~0u, bi, o);
                if (ok < bk || (ok == bk && oi < bi)) { bk = ok; bi = oi; }
            }
            if (lane == 0) g_knn[ob + r] = bi;
            #pragma unroll
            for (int i = 0; i < 8; ++i)
                if (ii[i] == bi) { dd[i] = INF; ii[i] = 0x7fffffff; }
        }
    }
}

// ---------------- mma GEMM (R13-proven) ----------------
#define MG_STGB  24576
#define MG_SMEM  (2*MG_STGB)

__global__ void __launch_bounds__(256, 2) k_mgemm(
    const __nv_bfloat16* __restrict__ Ah, const __nv_bfloat16* __restrict__ Al,
    const __nv_bfloat16* __restrict__ Bh, const __nv_bfloat16* __restrict__ Bl,
    const float* __restrict__ bias,
    float* Cf, __nv_bfloat16* Ch, __nv_bfloat16* Cl,
    int K, int ldc, int relu, int kvmode)
{
    extern __shared__ char sm[];
    uint32_t smb = smem_u32(sm);
    int t = threadIdx.x, lane = t & 31, w = t >> 5;
    int wm = w & 3, wn = w >> 2;
    int c0 = blockIdx.y * 64;
    int r0 = blockIdx.x * 128;
    int nch = K >> 5;

    float acc[2][4][4];
    #pragma unroll
    for (int i = 0; i < 2; ++i)
        #pragma unroll
        for (int j = 0; j < 4; ++j)
            #pragma unroll
            for (int e = 0; e < 4; ++e) acc[i][j][e] = 0.f;

    int lrow = lane & 15;
    int lcb  = (lane >> 4) * 16;

    auto issue = [&](int c, int stg) {
        int kc = c * 32;
        uint32_t Ab = smb + stg*MG_STGB;
        uint32_t Bb = Ab + 16384;
        #pragma unroll
        for (int i = 0; i < 4; ++i) {
            int e = t + i*256;
            int row = e >> 3, seg = e & 7;
            const __nv_bfloat16* src = (seg < 4 ? Ah : Al) + (size_t)(r0+row)*K + kc + (seg & 3)*8;
            CP16(Ab + swz((uint32_t)row*128 + seg*16), src);
        }
        #pragma unroll
        for (int i = 0; i < 2; ++i) {
            int e = t + i*256;
            int row = e >> 3, seg = e & 7;
            const __nv_bfloat16* src = (seg < 4 ? Bh : Bl) + (size_t)(c0+row)*K + kc + (seg & 3)*8;
            CP16(Bb + swz((uint32_t)row*128 + seg*16), src);
        }
    };

    issue(0, 0); CP_COMMIT();
    issue(1, 1); CP_COMMIT();

    for (int c = 0; c < nch; ++c) {
        CP_WAIT1();
        __syncthreads();
        uint32_t Ab = smb + (c & 1)*MG_STGB;
        uint32_t Bb = Ab + 16384;
        #pragma unroll
        for (int s = 0; s < 2; ++s) {
            int kb = s*32 + lcb;
            uint32_t ah[2][4], al[2][4];
            #pragma unroll
            for (int mb = 0; mb < 2; ++mb) {
                uint32_t ro = (uint32_t)(wm*32 + mb*16 + lrow)*128;
                ldsm4(ah[mb], Ab + swz(ro + kb));
                ldsm4(al[mb], Ab + swz(ro + 64 + kb));
            }
            #pragma unroll
            for (int nb = 0; nb < 2; ++nb) {
                uint32_t bh[4], bl[4];
                uint32_t ro = (uint32_t)(wn*32 + nb*16 + lrow)*128;
                ldsm4(bh, Bb + swz(ro + kb));
                ldsm4(bl, Bb + swz(ro + 64 + kb));
                #pragma unroll
                for (int mb = 0; mb < 2; ++mb) {
                    float* cA = acc[mb][nb*2];
                    float* cB = acc[mb][nb*2+1];
                    mma16816(cA, ah[mb], bh[0], bh[2]);
                    mma16816(cB, ah[mb], bh[1], bh[3]);
                    mma16816(cA, ah[mb], bl[0], bl[2]);
                    mma16816(cB, ah[mb], bl[1], bl[3]);
                    mma16816(cA, al[mb], bh[0], bh[2]);
                    mma16816(cB, al[mb], bh[1], bh[3]);
                }
            }
        }
        __syncthreads();
        if (c + 2 < nch) issue(c + 2, c & 1);
        CP_COMMIT();
    }

    int rbase = r0 + wm*32 + (lane >> 2);
    int cb = c0 + wn*32 + (lane & 3)*2;
    #pragma unroll
    for (int mb = 0; mb < 2; ++mb) {
        #pragma unroll
        for (int nn = 0; nn < 4; ++nn) {
            int col = cb + nn*8;
            float b0 = bias[col], b1 = bias[col+1];
            float v0 = acc[mb][nn][0] + b0, v1 = acc[mb][nn][1] + b1;
            float v2 = acc[mb][nn][2] + b0, v3 = acc[mb][nn][3] + b1;
            if (relu) {
                v0 = fmaxf(v0, 0.f); v1 = fmaxf(v1, 0.f);
                v2 = fmaxf(v2, 0.f); v3 = fmaxf(v3, 0.f);
            }
            int ra_row = rbase + mb*16, rb_row = rbase + mb*16 + 8;
            if (kvmode) {
                if (c0 < 256) {
                    *(float2*)(g_qf + (size_t)ra_row * DOUT + col) = make_float2(v0, v1);
                    *(float2*)(g_qf + (size_t)rb_row * DOUT + col) = make_float2(v2, v3);
                } else if (c0 < 512) {
                    int kc2 = col - 256;
                    *(unsigned*)(g_kvb + (size_t)ra_row * DOUT + kc2) = pk2(v0, v1);
                    *(unsigned*)(g_kvb + (size_t)rb_row * DOUT + kc2) = pk2(v2, v3);
                } else {
                    int vc2 = col - 512;
                    *(float2*)(g_vf + (size_t)ra_row * DOUT + vc2) = make_float2(v0, v1);
                    *(float2*)(g_vf + (size_t)rb_row * DOUT + vc2) = make_float2(v2, v3);
                }
            } else {
                size_t ra = (size_t)ra_row * ldc + col;
                size_t rb = (size_t)rb_row * ldc + col;
                if (Cf) {
                    *(float2*)(Cf + ra) = make_float2(v0, v1);
                    *(float2*)(Cf + rb) = make_float2(v2, v3);
                }
                if (Ch) {
                    float h0 = rndbf(v0), h1 = rndbf(v1), h2 = rndbf(v2), h3 = rndbf(v3);
                    *(unsigned*)(Ch + ra) = pk2(v0, v1);
                    *(unsigned*)(Cl + ra) = pk2(v0-h0, v1-h1);
                    *(unsigned*)(Ch + rb) = pk2(v2, v3);
                    *(unsigned*)(Cl + rb) = pk2(v2-h2, v3-h3);
                }
            }
        }
    }
}

// ---------------- fused pos GEMM ----------------
#define PG_A 0
#define PG_B 16384
#define PG_W 24576
#define SMEM_PG (24576 + 1024)

__global__ void __launch_bounds__(256) k_pgemm(
    const float* __restrict__ Wp1, const float* __restrict__ bp1,
    const float* __restrict__ bias)
{
    extern __shared__ char sm[];
    uint32_t smb = smem_u32(sm);
    float* ws = (float*)(sm + PG_W);
    int t = threadIdx.x, lane = t & 31, w = t >> 5;
    int wm = w & 3, wn = w >> 2;
    int r0 = blockIdx.x * 128;

    if (t < 192) ws[t] = Wp1[t];
    else ws[t] = bp1[t - 192];
    #pragma unroll 2
    for (int e = t; e < 512; e += 256) {
        int row = e >> 3, vo = e & 7;
        *(uint4*)(sm + PG_B + swz(row*128 + vo*16)) = *(const uint4*)(g_wp2T_h + row*64 + vo*8);
    }
    __syncthreads();

    {
        int row = t >> 1, ch = t & 1;
        int rr = r0 + row;
        int b = rr >> 17, n = (rr >> 4) & (NPTS - 1);
        int idx = g_knn[rr];
        float4 nbp = g_xyzw[(b << 13) + idx];
        float4 ctp = g_xyzw[(b << 13) + n];
        float rx = nbp.x - ctp.x, ry = nbp.y - ctp.y, rz = nbp.z - ctp.z;
        uint32_t hp[16];
        #pragma unroll
        for (int cc = 0; cc < 32; cc += 2) {
            int c = ch*32 + cc;
            float v0 = fmaf(rx, ws[c],   fmaf(ry, ws[64+c],   fmaf(rz, ws[128+c],   ws[192+c])));
            float v1 = fmaf(rx, ws[c+1], fmaf(ry, ws[64+c+1], fmaf(rz, ws[128+c+1], ws[192+c+1])));
            hp[cc>>1] = pk2(fmaxf(v0, 0.f), fmaxf(v1, 0.f));
        }
        uint32_t rbyte = (uint32_t)row*128 + ch*64;
        #pragma unroll
        for (int i = 0; i < 4; ++i)
            *(uint4*)(sm + PG_A + swz(rbyte + i*16)) = *(uint4*)&hp[i*4];
    }
    __syncthreads();

    float acc[2][4][4];
    #pragma unroll
    for (int i = 0; i < 2; ++i)
        #pragma unroll
        for (int j = 0; j < 4; ++j)
            #pragma unroll
            for (int e = 0; e < 4; ++e) acc[i][j][e] = 0.f;
    int lrow = lane & 15, lcolb = (lane >> 4) * 16;
    #pragma unroll
    for (int s = 0; s < 4; ++s) {
        int kb = s*32 + lcolb;
        uint32_t ah[2][4];
        #pragma unroll
        for (int mb = 0; mb < 2; ++mb)
            ldsm4(ah[mb], smb + PG_A + swz((uint32_t)(wm*32 + mb*16 + lrow)*128 + kb));
        #pragma unroll
        for (int nb = 0; nb < 2; ++nb) {
            uint32_t bh[4];
            ldsm4(bh, smb + PG_B + swz((uint32_t)(wn*32 + nb*16 + lrow)*128 + kb));
            #pragma unroll
            for (int mb = 0; mb < 2; ++mb) {
                mma16816(acc[mb][nb*2],   ah[mb], bh[0], bh[2]);
                mma16816(acc[mb][nb*2+1], ah[mb], bh[1], bh[3]);
            }
        }
    }

    int rbase = r0 + wm*32 + (lane >> 2);
    int cb = wn*32 + (lane & 3)*2;
    #pragma unroll
    for (int mb = 0; mb < 2; ++mb) {
        #pragma unroll
        for (int nn = 0; nn < 4; ++nn) {
            int col = cb + nn*8;
            float b0 = bias[col], b1 = bias[col+1];
            size_t ra = (size_t)(rbase + mb*16) * HD + col;
            size_t rb = (size_t)(rbase + mb*16 + 8) * HD + col;
            *(unsigned*)(g_posb + ra) = pk2(acc[mb][nn][0] + b0, acc[mb][nn][1] + b1);
            *(unsigned*)(g_posb + rb) = pk2(acc[mb][nn][2] + b0, acc[mb][nn][3] + b1);
        }
    }
}

// ---------------- fused attention (R13-proven) ----------------
__global__ void __launch_bounds__(128) k_attn(float* __restrict__ attn_out) {
    __shared__ int   idx_s[16];
    __shared__ float pos_s[16][68];
    __shared__ float k_s[16][260];
    __shared__ float q_s[256];
    __shared__ float logit_s[64];
    __shared__ float attn_s[64];
    int t  = threadIdx.x;
    int gp = blockIdx.x;
    int b  = gp >> 13, n = gp & (NPTS-1);

    if (t < 16) idx_s[t] = g_knn[gp*KNBR + t];
    if (t < 64) ((float4*)q_s)[t] = ((const float4*)(g_qf + (size_t)gp * DOUT))[t];
    {
        const uint2* ps = (const uint2*)(g_posb + (size_t)gp * KNBR * HD);
        #pragma unroll
        for (int e = t; e < 256; e += 128) {
            int jj = e >> 4, cc = e & 15;
            uint2 u = ps[e];
            float2 f0 = __bfloat1622float2(*(__nv_bfloat162*)&u.x);
            float2 f1 = __bfloat1622float2(*(__nv_bfloat162*)&u.y);
            *(float4*)&pos_s[jj][cc*4] = make_float4(f0.x, f0.y, f1.x, f1.y);
        }
    }
    __syncthreads();
    #pragma unroll
    for (int e = t; e < 1024; e += 128) {
        int jj = e >> 6, uu = e & 63;
        size_t rowb = ((size_t)b * NPTS + idx_s[jj]) * DOUT;
        uint2 u = ((const uint2*)(g_kvb + rowb))[uu];
        float2 f0 = __bfloat1622float2(*(__nv_bfloat162*)&u.x);
        float2 f1 = __bfloat1622float2(*(__nv_bfloat162*)&u.y);
        *(float4*)&k_s[jj][uu*4] = make_float4(f0.x, f0.y, f1.x, f1.y);
    }
    __syncthreads();
    {
        int p = t >> 1, half = t & 1;
        int jj = p & 15, h = p >> 4;
        float s = 0.f;
        int cbs = half * 32;
        #pragma unroll
        for (int c = 0; c < 32; ++c) {
            int cc = cbs + c;
            s = fmaf(q_s[h*64+cc], k_s[jj][h*64+cc] + pos_s[jj][cc], s);
        }
        s += __shfl_xor_sync(~0u, s, 1);
        if (half == 0) logit_s[h*16 + jj] = s * 0.125f;
    }
    __syncthreads();
    if (t < 64) {
        int h2 = t >> 4, j2 = t & 15;
        float l = logit_s[t];
        float mx = l;
        #pragma unroll
        for (int o = 8; o; o >>= 1) mx = fmaxf(mx, __shfl_xor_sync(~0u, mx, o));
        float ex = expf(l - mx);
        float sum = ex;
        #pragma unroll
        for (int o = 8; o; o >>= 1) sum += __shfl_xor_sync(~0u, sum, o);
        float a = ex / sum;
        attn_s[t] = a;
        attn_out[(((size_t)b*NH + h2) * NPTS + n) * KNBR + j2] = a;
    }
    __syncthreads();
    #pragma unroll
    for (int ee = 0; ee < 2; ++ee) {
        int e = t + ee*128;
        int h3 = e >> 6, c = e & 63;
        float s = 0.f;
        #pragma unroll
        for (int j = 0; j < 16; ++j) {
            float v = g_vf[((size_t)b * NPTS + idx_s[j]) * DOUT + e];
            s = fmaf(attn_s[h3*16 + j], v + pos_s[j][c], s);
        }
        float hs = rndbf(s);
        g_mid_h[(size_t)gp * DOUT + e] = __float2bfloat16_rn(s);
        g_mid_l[(size_t)gp * DOUT + e] = __float2bfloat16_rn(s - hs);
    }
}

// ---------------- final ----------------
__global__ void k_final(const float* __restrict__ g2, const float* __restrict__ b2,
                        float* __restrict__ out) {
    int warp = (blockIdx.x * blockDim.x + threadIdx.x) >> 5;
    int lane = threadIdx.x & 31;
    const float4* row = (const float4*)(g_fc2 + (size_t)warp * DOUT);
    float4 v0 = row[lane*2], v1 = row[lane*2+1];
    float s = v0.x+v0.y+v0.z+v0.w + v1.x+v1.y+v1.z+v1.w;
    #pragma unroll
    for (int o = 16; o; o >>= 1) s += __shfl_xor_sync(~0u, s, o);
    float mu = s * (1.f/256.f);
    float d0x=v0.x-mu, d0y=v0.y-mu, d0z=v0.z-mu, d0w=v0.w-mu;
    float d1x=v1.x-mu, d1y=v1.y-mu, d1z=v1.z-mu, d1w=v1.w-mu;
    float s2 = d0x*d0x+d0y*d0y+d0z*d0z+d0w*d0w + d1x*d1x+d1y*d1y+d1z*d1z+d1w*d1w;
    #pragma unroll
    for (int o = 16; o; o >>= 1) s2 += __shfl_xor_sync(~0u, s2, o);
    float rs = rsqrtf(s2 * (1.f/256.f) + 1e-5f);
    float4 gA = ((const float4*)g2)[lane*2],  gB = ((const float4*)g2)[lane*2+1];
    float4 bA = ((const float4*)b2)[lane*2],  bB = ((const float4*)b2)[lane*2+1];
    const float4* lq = (const float4*)(g_lnq + (size_t)warp * DOUT);
    float4 qA = lq[lane*2], qB = lq[lane*2+1];
    float4 oA, oB;
    oA.x = d0x*rs*gA.x + bA.x + qA.x; oA.y = d0y*rs*gA.y + bA.y + qA.y;
    oA.z = d0z*rs*gA.z + bA.z + qA.z; oA.w = d0w*rs*gA.w + bA.w + qA.w;
    oB.x = d1x*rs*gB.x + bB.x + qB.x; oB.y = d1y*rs*gB.y + bB.y + qB.y;
    oB.z = d1z*rs*gB.z + bB.z + qB.z; oB.w = d1w*rs*gB.w + bB.w + qB.w;
    float4* dst = (float4*)(out + (size_t)warp * DOUT);
    dst[lane*2]   = oA;
    dst[lane*2+1] = oB;
}

// ---------------- host launcher ----------------
extern "C" void kernel_launch(void* const* d_in, const int* in_sizes, int n_in,
                              void* d_out, int out_size) {
    const float* xyz      = (const float*)d_in[0];
    const float* features = (const float*)d_in[1];
    const float* Wq  = (const float*)d_in[2];
    const float* bq  = (const float*)d_in[3];
    const float* Wk  = (const float*)d_in[4];
    const float* bk  = (const float*)d_in[5];
    const float* Wv  = (const float*)d_in[6];
    const float* bv  = (const float*)d_in[7];
    const float* Wp1 = (const float*)d_in[8];
    const float* bp1 = (const float*)d_in[9];
    const float* Wp2 = (const float*)d_in[10];
    const float* bp2 = (const float*)d_in[11];
    const float* Wf1 = (const float*)d_in[12];
    const float* bf1 = (const float*)d_in[13];
    const float* Wf2 = (const float*)d_in[14];
    const float* bf2 = (const float*)d_in[15];
    const float* g1  = (const float*)d_in[16];
    const float* b1  = (const float*)d_in[17];
    const float* g2  = (const float*)d_in[18];
    const float* b2  = (const float*)d_in[19];

    float* out      = (float*)d_out;
    float* attn_out = out + (size_t)ROWS * DOUT;

    #define SYM(p, s) float* p; cudaGetSymbolAddress((void**)&p, s)
    #define SYMB(p, s) __nv_bfloat16* p; cudaGetSymbolAddress((void**)&p, s)
    SYMB(p_feat_h, g_feat_h); SYMB(p_feat_l, g_feat_l);
    SYMB(p_lnf_h,  g_lnf_h);  SYMB(p_lnf_l,  g_lnf_l);
    SYM(p_lnq, g_lnq); SYM(p_fc2, g_fc2);
    SYMB(p_mid_h, g_mid_h); SYMB(p_mid_l, g_mid_l);
    SYMB(p_fc1_h, g_fc1_h); SYMB(p_fc1_l, g_fc1_l);
    SYMB(p_wqkvT_h, g_wqkvT_h); SYMB(p_wqkvT_l, g_wqkvT_l);
    SYMB(p_wf1T_h, g_wf1T_h);   SYMB(p_wf1T_l, g_wf1T_l);
    SYMB(p_wf2T_h, g_wf2T_h);   SYMB(p_wf2T_l, g_wf2T_l);
    SYM(p_bqkv, g_bqkv);

    static cudaStream_t s2 = nullptr, s3 = nullptr;
    static cudaEvent_t evPrep = nullptr, evSide = nullptr, evLnq = nullptr;
    static bool attr_done = false;
    if (!attr_done) {
        cudaFuncSetAttribute(k_mgemm, cudaFuncAttributeMaxDynamicSharedMemorySize, MG_SMEM);
        cudaFuncSetAttribute(k_knn2,  cudaFuncAttributeMaxDynamicSharedMemorySize, SMEM_KNN);
        cudaFuncSetAttribute(k_pgemm, cudaFuncAttributeMaxDynamicSharedMemorySize, SMEM_PG);
        cudaStreamCreateWithFlags(&s2, cudaStreamNonBlocking);
        cudaStreamCreateWithFlags(&s3, cudaStreamNonBlocking);
        cudaEventCreateWithFlags(&evPrep, cudaEventDisableTiming);
        cudaEventCreateWithFlags(&evSide, cudaEventDisableTiming);
        cudaEventCreateWithFlags(&evLnq, cudaEventDisableTiming);
        attr_done = true;
    }

    // 1: pack (s2) — tiny, unblocks KNN immediately
    k_pack<<<128, 256, 0, s2>>>(xyz);
    // 2: prep (main)
    k_prep<<<PREP_BLOCKS, 256>>>(features, Wq, Wk, Wv, Wp2, Wf1, Wf2, g1, b1, bq, bk, bv);
    cudaEventRecord(evPrep, 0);
    // 3: qkv GEMM (main)
    {
        dim3 g(ROWS/128, 12);
        k_mgemm<<<g, 256, MG_SMEM>>>(p_feat_h, p_feat_l, p_wqkvT_h, p_wqkvT_l,
                                     p_bqkv, nullptr, nullptr, nullptr, DIM, 768, 0, 1);
    }
    // 4: knn (s2) — overlaps prep+qkv   <- profiler slot
    {
        dim3 kg(NPTS/64, BATCH);
        k_knn2<<<kg, 512, SMEM_KNN, s2>>>();
    }
    // 5: pos (s2) — needs knn (in-order) + Wp2T from prep
    cudaStreamWaitEvent(s2, evPrep, 0);
    k_pgemm<<<NROWS/128, 256, SMEM_PG, s2>>>(Wp1, bp1, bp2);
    cudaEventRecord(evSide, s2);

    // 6: lnq GEMM (s3)
    cudaStreamWaitEvent(s3, evPrep, 0);
    {
        dim3 g(ROWS/128, 4);
        k_mgemm<<<g, 256, MG_SMEM, s3>>>(p_lnf_h, p_lnf_l, p_wqkvT_h, p_wqkvT_l,
                                         bq, p_lnq, nullptr, nullptr, DIM, DOUT, 0, 0);
    }
    cudaEventRecord(evLnq, s3);

    // join, then attention
    cudaStreamWaitEvent(0, evSide, 0);
    k_attn<<<ROWS, 128>>>(attn_out);

    // fc1, fc2
    {
        dim3 g(ROWS/128, 4);
        k_mgemm<<<g, 256, MG_SMEM>>>(p_mid_h, p_mid_l, p_wf1T_h, p_wf1T_l,
                                     bf1, nullptr, p_fc1_h, p_fc1_l, DOUT, DOUT, 1, 0);
        k_mgemm<<<g, 256, MG_SMEM>>>(p_fc1_h, p_fc1_l, p_wf2T_h, p_wf2T_l,
                                     bf2, p_fc2, nullptr, nullptr, DOUT, DOUT, 0, 0);
    }

    // final (needs lnq)
    cudaStreamWaitEvent(0, evLnq, 0);
    k_final<<<ROWS/8, 256>>>(g2, b2, out);
}